// round 1
// baseline (speedup 1.0000x reference)
#include <cuda_runtime.h>

#define NATOMS 10000
#define NEDGES 100000
#define DTOT 40            // 1 + 3 + 9 + 27 uncoupled rows per atom
#define UNC 1280           // DTOT * 32 floats per atom
#define USZ 526            // 1 + 12 + 81 + 432
#define WSZ 2560           // 8*128 + 8*96 + 8*64 + 8*32
#define SSZ 142            // 1 + 6 + 27 + 108 per-edge S scalars
#define AB 4               // atoms per block in output kernel

// scratch (allocation-free rule: __device__ globals)
__device__ float g_uncf[(size_t)NATOMS * UNC];
__device__ float g_pool[(size_t)NATOMS * UNC];

// ---------------------------------------------------------------------------
// Kernel A: uncouple atom features.  unc_f[a, Doff_l + d, c] =
//   sum_m U_l[d,m] * feat_{lp(m)}[a, mp(m), lo_l + c]      (one warp per atom)
// ---------------------------------------------------------------------------
__global__ __launch_bounds__(256)
void k_uncouple_feat(const float* __restrict__ f0, const float* __restrict__ f1,
                     const float* __restrict__ f2, const float* __restrict__ f3,
                     const float* __restrict__ U0, const float* __restrict__ U1,
                     const float* __restrict__ U2, const float* __restrict__ U3)
{
    __shared__ float Ush[USZ];
    for (int i = threadIdx.x; i < USZ; i += blockDim.x) {
        float v;
        if (i < 1)       v = U0[i];
        else if (i < 13) v = U1[i - 1];
        else if (i < 94) v = U2[i - 13];
        else             v = U3[i - 94];
        Ush[i] = v;
    }
    __syncthreads();

    const int gw   = (blockIdx.x * blockDim.x + threadIdx.x) >> 5;
    const int lane = threadIdx.x & 31;
    if (gw >= NATOMS) return;
    const int a = gw;

    const float* feats[4] = {f0, f1, f2, f3};
    const int KK[4]   = {128, 96, 64, 32};
    const int LOv[4]  = {96, 64, 32, 0};
    const int DL[4]   = {1, 3, 9, 27};
    const int DOFF[4] = {0, 1, 4, 13};
    const int MLv[4]  = {1, 4, 9, 16};
    const int UOFF[4] = {0, 1, 13, 94};

    #pragma unroll
    for (int l = 0; l < 4; l++) {
        float F[16];
        int m = 0;
        #pragma unroll
        for (int lp = 0; lp <= l; lp++) {
            const float* fp = feats[lp];
            const int K = KK[lp];
            long base = (long)a * (2 * lp + 1) * K + LOv[l] + lane;
            #pragma unroll
            for (int mp = 0; mp < 2 * lp + 1; mp++)
                F[m++] = __ldg(fp + base + (long)mp * K);
        }
        float* ob = g_uncf + (long)a * UNC + DOFF[l] * 32 + lane;
        #pragma unroll
        for (int d = 0; d < DL[l]; d++) {
            float acc = 0.f;
            #pragma unroll
            for (int mm = 0; mm < MLv[l]; mm++)
                acc += Ush[UOFF[l] + d * MLv[l] + mm] * F[mm];
            ob[d * 32] = acc;
        }
    }
}

// ---------------------------------------------------------------------------
// Kernel B: per-edge.  Radial basis, S-trick uncouple, gather unc_f[neighbor],
// elementwise product, atomicAdd scatter into pooled[center].  Warp per edge,
// lane = channel (0..31).
// ---------------------------------------------------------------------------
__global__ __launch_bounds__(256)
void k_edge(const float* __restrict__ r,
            const float* __restrict__ sh0, const float* __restrict__ sh1,
            const float* __restrict__ sh2, const float* __restrict__ sh3,
            const float* __restrict__ W0, const float* __restrict__ W1,
            const float* __restrict__ W2, const float* __restrict__ W3,
            const float* __restrict__ U0, const float* __restrict__ U1,
            const float* __restrict__ U2, const float* __restrict__ U3,
            const int* __restrict__ centers, const int* __restrict__ neighbors)
{
    __shared__ float Wsh[WSZ];
    __shared__ float Ush[USZ];
    __shared__ float Ssh[8 * SSZ];   // 8 warps per 256-thread block

    for (int i = threadIdx.x; i < WSZ; i += blockDim.x) {
        float v;
        if (i < 1024)      v = W0[i];
        else if (i < 1792) v = W1[i - 1024];
        else if (i < 2304) v = W2[i - 1792];
        else               v = W3[i - 2304];
        Wsh[i] = v;
    }
    for (int i = threadIdx.x; i < USZ; i += blockDim.x) {
        float v;
        if (i < 1)       v = U0[i];
        else if (i < 13) v = U1[i - 1];
        else if (i < 94) v = U2[i - 13];
        else             v = U3[i - 94];
        Ush[i] = v;
    }
    __syncthreads();

    const int lane = threadIdx.x & 31;
    const int wid  = threadIdx.x >> 5;
    float* Sw = Ssh + wid * SSZ;
    const int nwarp = (gridDim.x * blockDim.x) >> 5;
    const int gw0   = (blockIdx.x * blockDim.x + threadIdx.x) >> 5;

    const float PI = 3.14159265358979323846f;

    for (int e = gw0; e < NEDGES; e += nwarp) {
        const float rr  = __ldg(r + e);
        const float inv = 1.f / (rr + 1e-6f);
        const float x   = rr * 0.2f;                      // r / CUTOFF
        const float fc  = 0.5f * (cosf(PI * fminf(x, 1.f)) + 1.f);
        const float t   = PI * x;
        const float pref = inv * fc;
        float rb[8];
        #pragma unroll
        for (int n = 0; n < 8; n++) rb[n] = sinf((float)(n + 1) * t) * pref;

        float shv[16];
        shv[0] = __ldg(sh0 + e);
        #pragma unroll
        for (int mp = 0; mp < 3; mp++) shv[1 + mp] = __ldg(sh1 + (long)e * 3 + mp);
        #pragma unroll
        for (int mp = 0; mp < 5; mp++) shv[4 + mp] = __ldg(sh2 + (long)e * 5 + mp);
        #pragma unroll
        for (int mp = 0; mp < 7; mp++) shv[9 + mp] = __ldg(sh3 + (long)e * 7 + mp);

        // per-edge scalars S[l, d, lp] = sum_m' U_l[d, lp^2+m'] * sh[lp, m']
        for (int p = lane; p < SSZ; p += 32) {
            int uo, ml, d, lp;
            if (p < 1)       { uo = 0;  ml = 1;  d = 0;          lp = 0; }
            else if (p < 7)  { int q = p - 1;  uo = 1;  ml = 4;  d = q >> 1; lp = q & 1; }
            else if (p < 34) { int q = p - 7;  uo = 13; ml = 9;  d = q / 3;  lp = q - 3 * (q / 3); }
            else             { int q = p - 34; uo = 94; ml = 16; d = q >> 2; lp = q & 3; }
            const float* Ur = Ush + uo + d * ml + lp * lp;
            float s = 0.f;
            for (int mp = 0; mp < 2 * lp + 1; mp++)
                s += Ur[mp] * shv[lp * lp + mp];
            Sw[p] = s;
        }
        __syncwarp();

        const int ctr = __ldg(centers + e);
        const int nbr = __ldg(neighbors + e);
        const float* fb = g_uncf + (long)nbr * UNC + lane;
        float*       pb = g_pool + (long)ctr * UNC + lane;

        const int KK[4]   = {128, 96, 64, 32};
        const int LOv[4]  = {96, 64, 32, 0};
        const int DL[4]   = {1, 3, 9, 27};
        const int DOFF[4] = {0, 1, 4, 13};
        const int WOFF[4] = {0, 1024, 1792, 2304};
        const int SOFF[4] = {0, 1, 7, 34};

        #pragma unroll
        for (int l = 0; l < 4; l++) {
            float rad[4];
            #pragma unroll
            for (int lp = 0; lp <= l; lp++) {
                const float* w = Wsh + WOFF[lp] + LOv[l] + lane;
                float acc = 0.f;
                #pragma unroll
                for (int n = 0; n < 8; n++) acc += rb[n] * w[n * KK[lp]];
                rad[lp] = acc;
            }
            const float* Sl = Sw + SOFF[l];
            #pragma unroll
            for (int d = 0; d < DL[l]; d++) {
                float u = 0.f;
                #pragma unroll
                for (int lp = 0; lp <= l; lp++)
                    u += Sl[d * (l + 1) + lp] * rad[lp];
                const int off = (DOFF[l] + d) * 32;
                atomicAdd(pb + off, u * __ldg(fb + off));
            }
        }
        __syncwarp();   // protect Sw reuse on next grid-stride iteration
    }
}

// ---------------------------------------------------------------------------
// Kernel C: per atom — couple pooled with U, concat into cat_l [2l+1, K_l],
// out_l = feat_l + cat_l @ Wlin_l.  AB atoms per 128-thread block.
// cat layout per atom: l=0 @0 (128), l=1 @128 (288), l=2 @416 (320), l=3 @736 (224)
// ---------------------------------------------------------------------------
__global__ __launch_bounds__(128)
void k_output(const float* __restrict__ f0, const float* __restrict__ f1,
              const float* __restrict__ f2, const float* __restrict__ f3,
              const float* __restrict__ U0, const float* __restrict__ U1,
              const float* __restrict__ U2, const float* __restrict__ U3,
              const float* __restrict__ L0, const float* __restrict__ L1,
              const float* __restrict__ L2, const float* __restrict__ L3,
              float* __restrict__ out)
{
    __shared__ float Ush[USZ];
    __shared__ float Psh[AB * UNC];
    __shared__ float Csh[AB * 960];
    const int tid = threadIdx.x;

    for (int i = tid; i < USZ; i += 128) {
        float v;
        if (i < 1)       v = U0[i];
        else if (i < 13) v = U1[i - 1];
        else if (i < 94) v = U2[i - 13];
        else             v = U3[i - 94];
        Ush[i] = v;
    }
    const int a0 = blockIdx.x * AB;
    for (int i = tid; i < AB * UNC; i += 128)
        Psh[i] = g_pool[(long)a0 * UNC + i];
    __syncthreads();

    // couple + concat -> Csh
    for (int idx = tid; idx < AB * 960; idx += 128) {
        const int a2 = idx / 960;
        const int ii = idx - 960 * a2;
        int l, co, Kl;
        if (ii < 128)      { l = 0; co = 0;   Kl = 128; }
        else if (ii < 416) { l = 1; co = 128; Kl = 96;  }
        else if (ii < 736) { l = 2; co = 416; Kl = 64;  }
        else               { l = 3; co = 736; Kl = 32;  }
        const int loc = ii - co;
        const int m   = loc / Kl;
        const int ch  = loc - m * Kl;
        const int b   = ch >> 5;
        const int c   = ch & 31;
        const int lp  = l + b;
        const int mm  = l * l + m;
        int uo, ml, dof, dc;
        if (lp == 0)      { uo = 0;  ml = 1;  dof = 0;  dc = 1;  }
        else if (lp == 1) { uo = 1;  ml = 4;  dof = 1;  dc = 3;  }
        else if (lp == 2) { uo = 13; ml = 9;  dof = 4;  dc = 9;  }
        else              { uo = 94; ml = 16; dof = 13; dc = 27; }
        const float* pp = Psh + a2 * UNC + dof * 32 + c;
        const float* uu = Ush + uo + mm;
        float acc = 0.f;
        for (int d = 0; d < dc; d++) acc += uu[d * ml] * pp[d * 32];
        Csh[idx] = acc;
    }
    __syncthreads();

    // l=0: [AB x 1 x 128] @ [128 x 128]
    {
        const int q = tid;
        float acc[AB] = {0.f, 0.f, 0.f, 0.f};
        for (int k = 0; k < 128; k++) {
            const float w = __ldg(L0 + k * 128 + q);
            #pragma unroll
            for (int a2 = 0; a2 < AB; a2++) acc[a2] += Csh[a2 * 960 + k] * w;
        }
        #pragma unroll
        for (int a2 = 0; a2 < AB; a2++) {
            const long a = a0 + a2;
            out[a * 128 + q] = __ldg(f0 + a * 128 + q) + acc[a2];
        }
    }
    // l=1: [AB x 3 x 96] @ [96 x 96]
    if (tid < 96) {
        const int q = tid;
        float acc[AB][3] = {};
        for (int k = 0; k < 96; k++) {
            const float w = __ldg(L1 + k * 96 + q);
            #pragma unroll
            for (int a2 = 0; a2 < AB; a2++)
                #pragma unroll
                for (int m = 0; m < 3; m++)
                    acc[a2][m] += Csh[a2 * 960 + 128 + m * 96 + k] * w;
        }
        #pragma unroll
        for (int a2 = 0; a2 < AB; a2++) {
            const long a = a0 + a2;
            #pragma unroll
            for (int m = 0; m < 3; m++)
                out[1280000 + (a * 3 + m) * 96 + q] =
                    __ldg(f1 + (a * 3 + m) * 96 + q) + acc[a2][m];
        }
    }
    // l=2: [AB x 5 x 64] @ [64 x 64]  (2 thread-groups x 2 atoms)
    {
        const int grp = tid >> 6, q = tid & 63;
        float acc[2][5] = {};
        for (int k = 0; k < 64; k++) {
            const float w = __ldg(L2 + k * 64 + q);
            #pragma unroll
            for (int j = 0; j < 2; j++)
                #pragma unroll
                for (int m = 0; m < 5; m++)
                    acc[j][m] += Csh[(grp * 2 + j) * 960 + 416 + m * 64 + k] * w;
        }
        #pragma unroll
        for (int j = 0; j < 2; j++) {
            const long a = a0 + grp * 2 + j;
            #pragma unroll
            for (int m = 0; m < 5; m++)
                out[4160000 + (a * 5 + m) * 64 + q] =
                    __ldg(f2 + (a * 5 + m) * 64 + q) + acc[j][m];
        }
    }
    // l=3: [AB x 7 x 32] @ [32 x 32]  (4 thread-groups x 1 atom)
    {
        const int grp = tid >> 5, q = tid & 31;
        float acc[7] = {};
        for (int k = 0; k < 32; k++) {
            const float w = __ldg(L3 + k * 32 + q);
            #pragma unroll
            for (int m = 0; m < 7; m++)
                acc[m] += Csh[grp * 960 + 736 + m * 32 + k] * w;
        }
        const long a = a0 + grp;
        #pragma unroll
        for (int m = 0; m < 7; m++)
            out[7360000 + (a * 7 + m) * 32 + q] =
                __ldg(f3 + (a * 7 + m) * 32 + q) + acc[m];
    }
}

// ---------------------------------------------------------------------------
// Launch.  Input binding is done by element count + occurrence order so it is
// robust to either signature-grouped or setup_inputs-interleaved metadata:
//   size 100000 occurrences (in order): r, sh0, centers, neighbors
//   size 1024 occurrences   (in order): Wrad0, Wlin3
//   all other sizes are unique.
// ---------------------------------------------------------------------------
extern "C" void kernel_launch(void* const* d_in, const int* in_sizes, int n_in,
                              void* d_out, int out_size)
{
    const float *r = 0, *sh0 = 0, *sh1 = 0, *sh2 = 0, *sh3 = 0;
    const float *f0 = 0, *f1 = 0, *f2 = 0, *f3 = 0;
    const float *W0 = 0, *W1 = 0, *W2 = 0, *W3 = 0;
    const float *U0 = 0, *U1 = 0, *U2 = 0, *U3 = 0;
    const float *L0 = 0, *L1 = 0, *L2 = 0, *L3 = 0;
    const int *centers = 0, *neighbors = 0;

    int n100k = 0, n1024 = 0;
    for (int i = 0; i < n_in; i++) {
        const void* p = d_in[i];
        switch (in_sizes[i]) {
            case 100000:
                if (n100k == 0)      r = (const float*)p;
                else if (n100k == 1) sh0 = (const float*)p;
                else if (n100k == 2) centers = (const int*)p;
                else                 neighbors = (const int*)p;
                n100k++;
                break;
            case 300000: sh1 = (const float*)p; break;
            case 500000: sh2 = (const float*)p; break;
            case 700000: sh3 = (const float*)p; break;
            case 1280000: f0 = (const float*)p; break;
            case 2880000: f1 = (const float*)p; break;
            case 3200000: f2 = (const float*)p; break;
            case 2240000: f3 = (const float*)p; break;
            case 768: W1 = (const float*)p; break;
            case 512: W2 = (const float*)p; break;
            case 256: W3 = (const float*)p; break;
            case 1:   U0 = (const float*)p; break;
            case 12:  U1 = (const float*)p; break;
            case 81:  U2 = (const float*)p; break;
            case 432: U3 = (const float*)p; break;
            case 16384: L0 = (const float*)p; break;
            case 9216:  L1 = (const float*)p; break;
            case 4096:  L2 = (const float*)p; break;
            case 1024:
                if (n1024 == 0) W0 = (const float*)p;
                else            L3 = (const float*)p;
                n1024++;
                break;
            default: break;
        }
    }
    float* out = (float*)d_out;

    void* poolPtr = 0;
    cudaGetSymbolAddress(&poolPtr, g_pool);
    cudaMemsetAsync(poolPtr, 0, (size_t)NATOMS * UNC * sizeof(float));

    k_uncouple_feat<<<(NATOMS * 32 + 255) / 256, 256>>>(f0, f1, f2, f3, U0, U1, U2, U3);
    k_edge<<<1024, 256>>>(r, sh0, sh1, sh2, sh3, W0, W1, W2, W3,
                          U0, U1, U2, U3, centers, neighbors);
    k_output<<<NATOMS / AB, 128>>>(f0, f1, f2, f3, U0, U1, U2, U3,
                                   L0, L1, L2, L3, out);
}